// round 14
// baseline (speedup 1.0000x reference)
#include <cuda_runtime.h>
#include <cuda_fp16.h>

#define N_USERS 100000
#define N_ITEMS 200000
#define N_NODES 300000
#define D       64
#define HYPER   128
#define NNZ_CNT 4000000
#define NODESD  (N_NODES * D)        /* 19,200,000 floats */

#define UB256 391                    /* ceil(100000/256) */
#define IB256 782                    /* ceil(200000/256) */
#define GRID_ROWS (UB256 + IB256)    /* 1173 */

#define SCAN_BLOCKS 293              /* ceil(300000/1024) */

typedef unsigned long long u64t;

// Scratch (device globals: no allocations allowed)
__device__ __half g_hh[NODESD];            // fp16 gather copy: emb, then h1 (38.4 MB)
__device__ float g_P[2 * D * D];           // P_u, P_i = W Wt
__device__ float g_M[2 * D * D];           // per-layer M = P S
// Zero-blob: g_S (parity x partition S accumulators) followed by g_cnt
// (histogram / scatter cursor). ONE memset clears both (keeps ncu launch
// numbering compact so kSpmm lands at the profiled slot).
#define S_BYTES (2 * 2 * D * D * (int)sizeof(float))   /* 65536 */
__device__ __align__(16) unsigned char g_zblob[S_BYTES + N_NODES * (int)sizeof(int)];
#define G_S   ((float*)g_zblob)
#define G_CNT ((int*)(g_zblob + S_BYTES))
__device__ int   g_offs[N_NODES + 1];
__device__ volatile u64t g_state[SCAN_BLOCKS];  // lookback scan state
__device__ int2  g_csr[NNZ_CNT];           // (col, val-bits) interleaved

// ---------------- packed f32x2 helpers ----------------
struct p4 { u64t lo, hi; };                // packed float4

__device__ __forceinline__ u64t pk2(float s) {
    u64t r;
    asm("mov.b64 %0, {%1,%1};" : "=l"(r) : "r"(__float_as_uint(s)));
    return r;
}
__device__ __forceinline__ void fma2(u64t& acc, u64t a, u64t b) {
    asm("fma.rn.f32x2 %0, %1, %2, %0;" : "+l"(acc) : "l"(a), "l"(b));
}
__device__ __forceinline__ float4 unpk(p4 v) {
    unsigned x, y, z, w;
    asm("mov.b64 {%0,%1}, %2;" : "=r"(x), "=r"(y) : "l"(v.lo));
    asm("mov.b64 {%0,%1}, %2;" : "=r"(z), "=r"(w) : "l"(v.hi));
    return make_float4(__uint_as_float(x), __uint_as_float(y),
                       __uint_as_float(z), __uint_as_float(w));
}

// ---------------- L2 policy / load helpers ----------------
__device__ __forceinline__ u64t mk_evict_last() {
    u64t pol;
    asm("createpolicy.fractional.L2::evict_last.b64 %0, 1.0;" : "=l"(pol));
    return pol;
}
__device__ __forceinline__ u64t mk_evict_first() {
    u64t pol;
    asm("createpolicy.fractional.L2::evict_first.b64 %0, 1.0;" : "=l"(pol));
    return pol;
}
__device__ __forceinline__ uint2 ld_el8(const void* p, u64t pol) {
    uint2 v;
    asm("ld.global.nc.L2::cache_hint.v2.b32 {%0,%1}, [%2], %3;"
        : "=r"(v.x), "=r"(v.y) : "l"(p), "l"(pol));
    return v;
}
__device__ __forceinline__ void st_el8(void* p, uint2 v, u64t pol) {
    asm volatile("st.global.L2::cache_hint.v2.b32 [%0], {%1,%2}, %3;"
                 :: "l"(p), "r"(v.x), "r"(v.y), "l"(pol) : "memory");
}
__device__ __forceinline__ void st_ef8(void* p, int2 v, u64t pol) {
    asm volatile("st.global.L2::cache_hint.v2.b32 [%0], {%1,%2}, %3;"
                 :: "l"(p), "r"(v.x), "r"(v.y), "l"(pol) : "memory");
}
__device__ __forceinline__ ulonglong2 ldg_u64x2(const float* p) {
    ulonglong2 v;
    asm("ld.global.nc.v2.u64 {%0,%1}, [%2];" : "=l"(v.x), "=l"(v.y) : "l"(p));
    return v;
}

__device__ __forceinline__ uint2 f4_to_h4(float4 v) {
    __half2 a = __floats2half2_rn(v.x, v.y);
    __half2 b = __floats2half2_rn(v.z, v.w);
    uint2 r;
    r.x = *reinterpret_cast<unsigned*>(&a);
    r.y = *reinterpret_cast<unsigned*>(&b);
    return r;
}

#define FMA4(acc, s, v) { (acc).x += (s)*(v).x; (acc).y += (s)*(v).y; \
                          (acc).z += (s)*(v).z; (acc).w += (s)*(v).w; }

__device__ __forceinline__ void red_add_v4(float* dst, float4 v) {
    asm volatile("red.global.add.v4.f32 [%0], {%1,%2,%3,%4};"
                 :: "l"(dst), "f"(v.x), "f"(v.y), "f"(v.z), "f"(v.w) : "memory");
}

// ---------------------------------------------------------------------------
// P = W @ W^T per partition. grid=(2), block=256.
// ---------------------------------------------------------------------------
__global__ void kP(const float* __restrict__ user_w, const float* __restrict__ item_w) {
    __shared__ float sW[D * 132];
    const int part = blockIdx.x;
    const float* W = (part == 0) ? user_w : item_w;
    for (int i = threadIdx.x; i < D * HYPER / 4; i += blockDim.x) {
        int r = i >> 5, c4 = i & 31;
        float4 v = __ldg((const float4*)(W + r * HYPER + c4 * 4));
        *(float4*)(sW + r * 132 + c4 * 4) = v;
    }
    __syncthreads();
    const int rg = threadIdx.x >> 4, cg = threadIdx.x & 15;
    const int r0 = rg * 4, c0 = cg * 4;
    float acc[4][4] = {};
    for (int k = 0; k < HYPER; k += 4) {
        float4 a[4], b[4];
#pragma unroll
        for (int i = 0; i < 4; i++) a[i] = *(float4*)(sW + (r0 + i) * 132 + k);
#pragma unroll
        for (int j = 0; j < 4; j++) b[j] = *(float4*)(sW + (c0 + j) * 132 + k);
#pragma unroll
        for (int i = 0; i < 4; i++)
#pragma unroll
            for (int j = 0; j < 4; j++)
                acc[i][j] += a[i].x*b[j].x + a[i].y*b[j].y + a[i].z*b[j].z + a[i].w*b[j].w;
    }
    float* Pout = g_P + part * D * D;
#pragma unroll
    for (int i = 0; i < 4; i++)
#pragma unroll
        for (int j = 0; j < 4; j++)
            Pout[(r0 + i) * D + c0 + j] = acc[i][j];
}

// ---------------------------------------------------------------------------
// M = P @ S per partition. grid=(2), block=256.
// ---------------------------------------------------------------------------
__global__ void kM(int parity) {
    __shared__ float sP[D * 68];
    __shared__ float sS[D * 68];
    const int part = blockIdx.x;
    const float* P = g_P + part * D * D;
    const float* S = G_S + (parity * 2 + part) * D * D;
    for (int i = threadIdx.x; i < D * D / 4; i += blockDim.x) {
        int r = i >> 4, c4 = i & 15;
        *(float4*)(sP + r * 68 + c4 * 4) = *(const float4*)(P + r * D + c4 * 4);
        *(float4*)(sS + r * 68 + c4 * 4) = *(const float4*)(S + r * D + c4 * 4);
    }
    __syncthreads();
    const int rg = threadIdx.x >> 4, cg = threadIdx.x & 15;
    const int r0 = rg * 4, c0 = cg * 4;
    float4 acc[4] = {};
    for (int k = 0; k < D; k += 4) {
        float4 a[4], m[4];
#pragma unroll
        for (int i = 0; i < 4; i++) a[i] = *(float4*)(sP + (r0 + i) * 68 + k);
#pragma unroll
        for (int j = 0; j < 4; j++) m[j] = *(float4*)(sS + (k + j) * 68 + c0);
#pragma unroll
        for (int i = 0; i < 4; i++) {
            FMA4(acc[i], a[i].x, m[0]); FMA4(acc[i], a[i].y, m[1]);
            FMA4(acc[i], a[i].z, m[2]); FMA4(acc[i], a[i].w, m[3]);
        }
    }
    float* Mout = g_M + part * D * D;
#pragma unroll
    for (int i = 0; i < 4; i++) *(float4*)(Mout + (r0 + i) * D + c0) = acc[i];
}

// ---------------------------------------------------------------------------
// CSR build: histogram (+ scan-state reset) -> lookback scan -> scatter
// ---------------------------------------------------------------------------
__global__ void kHist(const int* __restrict__ rows) {
    int i = blockIdx.x * blockDim.x + threadIdx.x;
    if (i < SCAN_BLOCKS) g_state[i] = 0;
    int base = i * 4;
    if (base < NNZ_CNT) {
        int4 r = __ldg((const int4*)(rows + base));
        atomicAdd(&G_CNT[r.x], 1);
        atomicAdd(&G_CNT[r.y], 1);
        atomicAdd(&G_CNT[r.z], 1);
        atomicAdd(&G_CNT[r.w], 1);
    }
}

__global__ void __launch_bounds__(1024) kScan() {
    __shared__ int wsum[32];
    __shared__ int s_bt;
    __shared__ int s_run;
    const int t = threadIdx.x, bid = blockIdx.x;
    const int i = bid * 1024 + t;
    int v = (i < N_NODES) ? G_CNT[i] : 0;
    int incl = v;
#pragma unroll
    for (int d = 1; d < 32; d <<= 1) {
        int u = __shfl_up_sync(0xffffffffu, incl, d);
        if ((t & 31) >= d) incl += u;
    }
    if ((t & 31) == 31) wsum[t >> 5] = incl;
    __syncthreads();
    if (t < 32) {
        int w = wsum[t];
        int winc = w;
#pragma unroll
        for (int d = 1; d < 32; d <<= 1) {
            int u = __shfl_up_sync(0xffffffffu, winc, d);
            if (t >= d) winc += u;
        }
        wsum[t] = winc - w;            // exclusive warp offset
        if (t == 31) s_bt = winc;      // block total
    }
    __syncthreads();
    const int blockTotal = s_bt;
    if (t == 0) {
        if (bid == 0) {
            g_state[0] = ((u64t)2 << 32) | (unsigned)blockTotal;
            s_run = 0;
        } else {
            g_state[bid] = ((u64t)1 << 32) | (unsigned)blockTotal;
            __threadfence();
            int run = 0;
            int p = bid - 1;
            while (p >= 0) {
                u64t s;
                do { s = g_state[p]; } while ((s >> 32) == 0);
                run += (int)(unsigned)s;
                if ((s >> 32) == 2) break;
                p--;
            }
            g_state[bid] = ((u64t)2 << 32) | (unsigned)(run + blockTotal);
            __threadfence();
            s_run = run;
        }
    }
    __syncthreads();
    if (i < N_NODES) {
        int base = s_run + (incl - v) + wsum[t >> 5];
        g_offs[i] = base;
        G_CNT[i] = base;               // scatter cursor
    }
    if (i == 0) g_offs[N_NODES] = NNZ_CNT;
}

__global__ void kScatter(const int* __restrict__ rows, const int* __restrict__ cols,
                         const float* __restrict__ vals) {
    int i = blockIdx.x * blockDim.x + threadIdx.x;
    int base = i * 4;
    if (base >= NNZ_CNT) return;
    const u64t pol = mk_evict_first();
    int4 r = __ldg((const int4*)(rows + base));
    int4 c = __ldg((const int4*)(cols + base));
    float4 v = __ldg((const float4*)(vals + base));
    int p0 = atomicAdd(&G_CNT[r.x], 1);
    st_ef8(&g_csr[p0], make_int2(c.x, __float_as_int(v.x)), pol);
    int p1 = atomicAdd(&G_CNT[r.y], 1);
    st_ef8(&g_csr[p1], make_int2(c.y, __float_as_int(v.y)), pol);
    int p2 = atomicAdd(&G_CNT[r.z], 1);
    st_ef8(&g_csr[p2], make_int2(c.z, __float_as_int(v.z)), pol);
    int p3 = atomicAdd(&G_CNT[r.w], 1);
    st_ef8(&g_csr[p3], make_int2(c.w, __float_as_int(v.w)), pol);
}

// ---------------------------------------------------------------------------
// CSR SpMM over fp16 rows in g_hh (emb for layer 0, h1 for layer 1).
// One warp per row; half-warps alternate edges, 2-way unrolled.
// ---------------------------------------------------------------------------
__global__ void __launch_bounds__(256) kSpmm(float* __restrict__ gcn) {
    const int row = (blockIdx.x * blockDim.x + threadIdx.x) >> 5;
    if (row >= N_NODES) return;
    const int lane = threadIdx.x & 31;
    const int half = lane >> 4, l16 = lane & 15;
    const u64t pol = mk_evict_last();
    const int s = __ldg(&g_offs[row]);
    const int e = __ldg(&g_offs[row + 1]);
    float4 acc0 = make_float4(0.f, 0.f, 0.f, 0.f);
    float4 acc1 = make_float4(0.f, 0.f, 0.f, 0.f);
    int j = s + half;
    for (; j + 2 < e; j += 4) {
        int2 cva = __ldcs(&g_csr[j]);
        int2 cvb = __ldcs(&g_csr[j + 2]);
        float va = __int_as_float(cva.y);
        float vb = __int_as_float(cvb.y);
        uint2 ha = ld_el8(g_hh + (size_t)cva.x * D + l16 * 4, pol);
        uint2 hb = ld_el8(g_hh + (size_t)cvb.x * D + l16 * 4, pol);
        float2 a0 = __half22float2(*reinterpret_cast<__half2*>(&ha.x));
        float2 a1 = __half22float2(*reinterpret_cast<__half2*>(&ha.y));
        float2 b0 = __half22float2(*reinterpret_cast<__half2*>(&hb.x));
        float2 b1 = __half22float2(*reinterpret_cast<__half2*>(&hb.y));
        acc0.x += va * a0.x; acc0.y += va * a0.y; acc0.z += va * a1.x; acc0.w += va * a1.y;
        acc1.x += vb * b0.x; acc1.y += vb * b0.y; acc1.z += vb * b1.x; acc1.w += vb * b1.y;
    }
    if (j < e) {
        int2 cv = __ldcs(&g_csr[j]);
        float v = __int_as_float(cv.y);
        uint2 hv = ld_el8(g_hh + (size_t)cv.x * D + l16 * 4, pol);
        float2 f0 = __half22float2(*reinterpret_cast<__half2*>(&hv.x));
        float2 f1 = __half22float2(*reinterpret_cast<__half2*>(&hv.y));
        acc0.x += v * f0.x; acc0.y += v * f0.y; acc0.z += v * f1.x; acc0.w += v * f1.y;
    }
    acc0.x += acc1.x; acc0.y += acc1.y; acc0.z += acc1.z; acc0.w += acc1.w;
    acc0.x += __shfl_xor_sync(0xffffffffu, acc0.x, 16);
    acc0.y += __shfl_xor_sync(0xffffffffu, acc0.y, 16);
    acc0.z += __shfl_xor_sync(0xffffffffu, acc0.z, 16);
    acc0.w += __shfl_xor_sync(0xffffffffu, acc0.w, 16);
    if (half == 0)
        *(float4*)(gcn + (size_t)row * D + l16 * 4) = acc0;
}

// ---------------------------------------------------------------------------
// Partition mapping helper for row-tiled kernels (block = 256 rows)
// ---------------------------------------------------------------------------
struct PartInfo { int part, rowbase, partEnd, localOff; const float* emb; };

__device__ __forceinline__ PartInfo get_part(int b, const float* ue, const float* ie) {
    PartInfo p;
    if (b < UB256) { p.part = 0; p.rowbase = b * 256; p.partEnd = N_USERS; p.localOff = 0; p.emb = ue; }
    else { p.part = 1; p.rowbase = N_USERS + (b - UB256) * 256; p.partEnd = N_NODES; p.localOff = N_USERS; p.emb = ie; }
    return p;
}

// ---------------------------------------------------------------------------
// kS0: S0 = emb^T emb per partition; also emits fp16 emb copy into g_hh
// ---------------------------------------------------------------------------
__global__ void __launch_bounds__(256) kS0(const float* __restrict__ user_emb,
                                           const float* __restrict__ item_emb) {
    __shared__ float sA[64 * D];
    PartInfo p = get_part(blockIdx.x, user_emb, item_emb);
    const int tid = threadIdx.x;
    const int ag = tid >> 4, bg = tid & 15;
    const u64t pol = mk_evict_last();
    p4 sacc[4] = {};
    for (int t = 0; t < 4; t++) {
        const int tb = p.rowbase + t * 64;
        for (int i = tid; i < 1024; i += 256) {
            int r = i >> 4, c4 = i & 15;
            int gr = tb + r;
            float4 v = make_float4(0.f, 0.f, 0.f, 0.f);
            if (gr < p.partEnd) {
                v = __ldg((const float4*)(p.emb + (size_t)(gr - p.localOff) * D + c4 * 4));
                st_el8(g_hh + (size_t)gr * D + c4 * 4, f4_to_h4(v), pol);
            }
            *(float4*)(sA + r * D + c4 * 4) = v;
        }
        __syncthreads();
#pragma unroll 4
        for (int r = 0; r < 64; r++) {
            float4 a4 = *(float4*)(sA + r * D + ag * 4);
            ulonglong2 b2 = *(const ulonglong2*)(sA + r * D + bg * 4);
            u64t s;
            s = pk2(a4.x); fma2(sacc[0].lo, s, b2.x); fma2(sacc[0].hi, s, b2.y);
            s = pk2(a4.y); fma2(sacc[1].lo, s, b2.x); fma2(sacc[1].hi, s, b2.y);
            s = pk2(a4.z); fma2(sacc[2].lo, s, b2.x); fma2(sacc[2].hi, s, b2.y);
            s = pk2(a4.w); fma2(sacc[3].lo, s, b2.x); fma2(sacc[3].hi, s, b2.y);
        }
        __syncthreads();
    }
    float* Sdst = G_S + p.part * D * D;   // parity 0
#pragma unroll
    for (int j = 0; j < 4; j++)
        red_add_v4(Sdst + (ag * 4 + j) * D + bg * 4, unpk(sacc[j]));
}

// ---------------------------------------------------------------------------
// Epilogue. layer==0: hg0 = emb@M0; h1 = gcn0+hg0 -> g_hh (fp16, evict_last);
//                     accumulate S1 = emb^T h1 (exact fp32 from smem).
// layer==1: hg1 = emb@M1; h2 = gcn1+hg1; hidden_sum = emb + h1(fp16) + h2.
// M is read straight from L2/L1 via ld.global.nc (16 KB hot working set) so
// smem drops to 32 KB; __launch_bounds__(256,5) pushes occupancy 4->5 blk/SM.
// ---------------------------------------------------------------------------
__global__ void __launch_bounds__(256, 5) kEpi(const float* __restrict__ user_emb,
                                               const float* __restrict__ item_emb,
                                               const float* __restrict__ gcn,
                                               float* __restrict__ hg_out,
                                               float* __restrict__ hidden_sum,
                                               int layer) {
    __shared__ float sA[64 * D];
    __shared__ float sH[64 * D];
    PartInfo p = get_part(blockIdx.x, user_emb, item_emb);
    const int tid = threadIdx.x;
    const u64t pol = mk_evict_last();
    const float* Mg = g_M + p.part * D * D;
    const int rg = tid >> 4, cg = tid & 15;
    const int r0 = rg * 4, c0 = cg * 4;
    p4 sacc[4] = {};
    for (int t = 0; t < 4; t++) {
        const int tb = p.rowbase + t * 64;
        for (int i = tid; i < 1024; i += 256) {
            int r = i >> 4, c4 = i & 15;
            int gr = tb + r;
            float4 v = make_float4(0.f, 0.f, 0.f, 0.f);
            if (gr < p.partEnd)
                v = __ldg((const float4*)(p.emb + (size_t)(gr - p.localOff) * D + c4 * 4));
            *(float4*)(sA + r * D + c4 * 4) = v;
        }
        __syncthreads();
        // hg tile: acc = sA(rows) @ M (M via ld.global.nc, L1-hot), f32x2
        p4 acc[4] = {};
        for (int k = 0; k < D; k += 4) {
            float4 a[4]; ulonglong2 m[4];
#pragma unroll
            for (int i = 0; i < 4; i++) a[i] = *(float4*)(sA + (r0 + i) * D + k);
#pragma unroll
            for (int j = 0; j < 4; j++) m[j] = ldg_u64x2(Mg + (k + j) * D + c0);
#pragma unroll
            for (int i = 0; i < 4; i++) {
                u64t s;
                s = pk2(a[i].x); fma2(acc[i].lo, s, m[0].x); fma2(acc[i].hi, s, m[0].y);
                s = pk2(a[i].y); fma2(acc[i].lo, s, m[1].x); fma2(acc[i].hi, s, m[1].y);
                s = pk2(a[i].z); fma2(acc[i].lo, s, m[2].x); fma2(acc[i].hi, s, m[2].y);
                s = pk2(a[i].w); fma2(acc[i].lo, s, m[3].x); fma2(acc[i].hi, s, m[3].y);
            }
        }
#pragma unroll
        for (int i = 0; i < 4; i++) {
            int gr = tb + r0 + i;
            if (gr < p.partEnd) {
                size_t idx = (size_t)gr * D + c0;
                float4 hg = unpk(acc[i]);
                float4 g = __ldg((const float4*)(gcn + idx));
                *(float4*)(hg_out + idx) = hg;
                float4 hn = make_float4(hg.x + g.x, hg.y + g.y, hg.z + g.z, hg.w + g.w);
                if (layer == 0) {
                    st_el8(g_hh + idx, f4_to_h4(hn), pol);   // h1 fp16, keep resident
                    *(float4*)(sH + (r0 + i) * D + c0) = hn;
                } else {
                    uint2 hu = *(const uint2*)(g_hh + idx);  // h1 fp16
                    float2 h1a = __half22float2(*reinterpret_cast<__half2*>(&hu.x));
                    float2 h1b = __half22float2(*reinterpret_cast<__half2*>(&hu.y));
                    float4 e4 = *(float4*)(sA + (r0 + i) * D + c0);
                    float4 hs = make_float4(e4.x + h1a.x + hn.x, e4.y + h1a.y + hn.y,
                                            e4.z + h1b.x + hn.z, e4.w + h1b.y + hn.w);
                    *(float4*)(hidden_sum + idx) = hs;
                }
            } else if (layer == 0) {
                *(float4*)(sH + (r0 + i) * D + c0) = make_float4(0.f, 0.f, 0.f, 0.f);
            }
        }
        __syncthreads();
        if (layer == 0) {
#pragma unroll 4
            for (int r = 0; r < 64; r++) {
                float4 a4 = *(float4*)(sA + r * D + rg * 4);
                ulonglong2 h2 = *(const ulonglong2*)(sH + r * D + cg * 4);
                u64t s;
                s = pk2(a4.x); fma2(sacc[0].lo, s, h2.x); fma2(sacc[0].hi, s, h2.y);
                s = pk2(a4.y); fma2(sacc[1].lo, s, h2.x); fma2(sacc[1].hi, s, h2.y);
                s = pk2(a4.z); fma2(sacc[2].lo, s, h2.x); fma2(sacc[2].hi, s, h2.y);
                s = pk2(a4.w); fma2(sacc[3].lo, s, h2.x); fma2(sacc[3].hi, s, h2.y);
            }
            __syncthreads();
        }
    }
    if (layer == 0) {
        float* Sdst = G_S + (2 + p.part) * D * D;     // parity 1
#pragma unroll
        for (int j = 0; j < 4; j++)
            red_add_v4(Sdst + (rg * 4 + j) * D + cg * 4, unpk(sacc[j]));
    }
}

// ---------------------------------------------------------------------------
extern "C" void kernel_launch(void* const* d_in, const int* in_sizes, int n_in,
                              void* d_out, int out_size) {
    const float* user_emb = (const float*)d_in[0];
    const float* item_emb = (const float*)d_in[1];
    const float* user_w   = (const float*)d_in[2];
    const float* item_w   = (const float*)d_in[3];
    const float* adj_vals = (const float*)d_in[4];
    const int*   adj_rows = (const int*)d_in[5];
    const int*   adj_cols = (const int*)d_in[6];
    float* out = (float*)d_out;

    // Lazily created side stream + events (first call precedes graph capture;
    // fork/join via events is graph-capture legal). No device memory involved.
    static cudaStream_t s2 = nullptr;
    static cudaEvent_t evZ = nullptr, evS0 = nullptr, evM0 = nullptr,
                       evE0 = nullptr, evM1 = nullptr;
    if (!s2) {
        cudaStreamCreateWithFlags(&s2, cudaStreamNonBlocking);
        cudaEventCreateWithFlags(&evZ, cudaEventDisableTiming);
        cudaEventCreateWithFlags(&evS0, cudaEventDisableTiming);
        cudaEventCreateWithFlags(&evM0, cudaEventDisableTiming);
        cudaEventCreateWithFlags(&evE0, cudaEventDisableTiming);
        cudaEventCreateWithFlags(&evM1, cudaEventDisableTiming);
    }

    // d_out layout (floats): [0) hidden_sum(user_out|item_out) 19.2M
    //                        [19.2M) gcn_hidden L0,L1           38.4M
    //                        [57.6M) hgnn_hidden L0,L1          38.4M
    float* gcn0 = out + (size_t)NODESD * 1;
    float* gcn1 = out + (size_t)NODESD * 2;
    float* hg0  = out + (size_t)NODESD * 3;
    float* hg1  = out + (size_t)NODESD * 4;

    void* zAddr = nullptr; cudaGetSymbolAddress(&zAddr, g_zblob);

    const int EB4 = (NNZ_CNT / 4 + 255) / 256;   // 3907

    // Launch order chosen so ncu's "-s 5 -c 1" capture lands on kSpmm (#6).
    // 1: zero blob (g_S + g_cnt)
    cudaMemsetAsync(zAddr, 0, sizeof(g_zblob));
    cudaEventRecord(evZ, 0);
    // 2-4: CSR build (main stream)
    kHist<<<EB4, 256>>>(adj_rows);
    kScan<<<SCAN_BLOCKS, 1024>>>();
    kScatter<<<EB4, 256>>>(adj_rows, adj_cols, adj_vals);
    // 5: kS0 on side stream (needs g_S zeroed); emits fp16 emb -> g_hh
    cudaStreamWaitEvent(s2, evZ, 0);
    kS0<<<GRID_ROWS, 256, 0, s2>>>(user_emb, item_emb);
    cudaEventRecord(evS0, s2);
    // 6: layer-0 SpMM (after scatter [stream] + g_hh [event])   <-- profiled
    cudaStreamWaitEvent(0, evS0, 0);
    kSpmm<<<(N_NODES * 32) / 256, 256>>>(gcn0);
    // 7-8: kP, kM0 on side stream (tiny; overlap spmm0 harmlessly)
    kP<<<2, 256, 0, s2>>>(user_w, item_w);
    kM<<<2, 256, 0, s2>>>(0);
    cudaEventRecord(evM0, s2);
    // 9: epilogue 0 (needs gcn0 [stream] + M0 [event]); writes h1 fp16 + S1
    cudaStreamWaitEvent(0, evM0, 0);
    kEpi<<<GRID_ROWS, 256>>>(user_emb, item_emb, gcn0, hg0, out, 0);
    cudaEventRecord(evE0, 0);
    // 10: kM1 on side stream (needs S1 from epi0)
    cudaStreamWaitEvent(s2, evE0, 0);
    kM<<<2, 256, 0, s2>>>(1);
    cudaEventRecord(evM1, s2);
    // 11: layer-1 SpMM (g_hh = h1, written by epi0 on this stream)
    kSpmm<<<(N_NODES * 32) / 256, 256>>>(gcn1);
    // 12: epilogue 1 (needs gcn1 [stream] + M1 [event])
    cudaStreamWaitEvent(0, evM1, 0);
    kEpi<<<GRID_ROWS, 256>>>(user_emb, item_emb, gcn1, hg1, out, 1);
}

// round 16
// speedup vs baseline: 1.3576x; 1.3576x over previous
#include <cuda_runtime.h>
#include <cuda_fp16.h>

#define N_USERS 100000
#define N_ITEMS 200000
#define N_NODES 300000
#define D       64
#define HYPER   128
#define NNZ_CNT 4000000
#define NODESD  (N_NODES * D)        /* 19,200,000 floats */

#define UB256 391                    /* ceil(100000/256) */
#define IB256 782                    /* ceil(200000/256) */
#define GRID_ROWS (UB256 + IB256)    /* 1173 */

#define SCAN_BLOCKS 293              /* ceil(300000/1024) */

typedef unsigned long long u64t;

// Scratch (device globals: no allocations allowed)
__device__ __half g_hh[NODESD];            // fp16 gather copy: emb, then h1 (38.4 MB)
__device__ float g_P[2 * D * D];           // P_u, P_i = W Wt
__device__ float g_M[2 * D * D];           // per-layer M = P S
// Zero-blob: g_S followed by g_cnt; ONE memset clears both.
#define S_BYTES (2 * 2 * D * D * (int)sizeof(float))   /* 65536 */
__device__ __align__(16) unsigned char g_zblob[S_BYTES + N_NODES * (int)sizeof(int)];
#define G_S   ((float*)g_zblob)
#define G_CNT ((int*)(g_zblob + S_BYTES))
__device__ int   g_offs[N_NODES + 1];
__device__ volatile u64t g_state[SCAN_BLOCKS];  // lookback scan state
__device__ int2  g_csr[NNZ_CNT];           // (col, val-bits) interleaved

// ---------------- packed f32x2 helpers ----------------
struct p4 { u64t lo, hi; };                // packed float4

__device__ __forceinline__ u64t pk2(float s) {
    u64t r;
    asm("mov.b64 %0, {%1,%1};" : "=l"(r) : "r"(__float_as_uint(s)));
    return r;
}
__device__ __forceinline__ void fma2(u64t& acc, u64t a, u64t b) {
    asm("fma.rn.f32x2 %0, %1, %2, %0;" : "+l"(acc) : "l"(a), "l"(b));
}
__device__ __forceinline__ float4 unpk(p4 v) {
    unsigned x, y, z, w;
    asm("mov.b64 {%0,%1}, %2;" : "=r"(x), "=r"(y) : "l"(v.lo));
    asm("mov.b64 {%0,%1}, %2;" : "=r"(z), "=r"(w) : "l"(v.hi));
    return make_float4(__uint_as_float(x), __uint_as_float(y),
                       __uint_as_float(z), __uint_as_float(w));
}

// ---------------- L2 policy / load helpers ----------------
__device__ __forceinline__ u64t mk_evict_last() {
    u64t pol;
    asm("createpolicy.fractional.L2::evict_last.b64 %0, 1.0;" : "=l"(pol));
    return pol;
}
__device__ __forceinline__ u64t mk_evict_first() {
    u64t pol;
    asm("createpolicy.fractional.L2::evict_first.b64 %0, 1.0;" : "=l"(pol));
    return pol;
}
__device__ __forceinline__ uint2 ld_el8(const void* p, u64t pol) {
    uint2 v;
    asm("ld.global.nc.L2::cache_hint.v2.b32 {%0,%1}, [%2], %3;"
        : "=r"(v.x), "=r"(v.y) : "l"(p), "l"(pol));
    return v;
}
__device__ __forceinline__ void st_el8(void* p, uint2 v, u64t pol) {
    asm volatile("st.global.L2::cache_hint.v2.b32 [%0], {%1,%2}, %3;"
                 :: "l"(p), "r"(v.x), "r"(v.y), "l"(pol) : "memory");
}
__device__ __forceinline__ void st_ef8(void* p, int2 v, u64t pol) {
    asm volatile("st.global.L2::cache_hint.v2.b32 [%0], {%1,%2}, %3;"
                 :: "l"(p), "r"(v.x), "r"(v.y), "l"(pol) : "memory");
}

__device__ __forceinline__ uint2 f4_to_h4(float4 v) {
    __half2 a = __floats2half2_rn(v.x, v.y);
    __half2 b = __floats2half2_rn(v.z, v.w);
    uint2 r;
    r.x = *reinterpret_cast<unsigned*>(&a);
    r.y = *reinterpret_cast<unsigned*>(&b);
    return r;
}

#define FMA4(acc, s, v) { (acc).x += (s)*(v).x; (acc).y += (s)*(v).y; \
                          (acc).z += (s)*(v).z; (acc).w += (s)*(v).w; }

__device__ __forceinline__ void red_add_v4(float* dst, float4 v) {
    asm volatile("red.global.add.v4.f32 [%0], {%1,%2,%3,%4};"
                 :: "l"(dst), "f"(v.x), "f"(v.y), "f"(v.z), "f"(v.w) : "memory");
}

// ---------------------------------------------------------------------------
// P = W @ W^T per partition. grid=(2), block=256.
// ---------------------------------------------------------------------------
__global__ void kP(const float* __restrict__ user_w, const float* __restrict__ item_w) {
    __shared__ float sW[D * 132];
    const int part = blockIdx.x;
    const float* W = (part == 0) ? user_w : item_w;
    for (int i = threadIdx.x; i < D * HYPER / 4; i += blockDim.x) {
        int r = i >> 5, c4 = i & 31;
        float4 v = __ldg((const float4*)(W + r * HYPER + c4 * 4));
        *(float4*)(sW + r * 132 + c4 * 4) = v;
    }
    __syncthreads();
    const int rg = threadIdx.x >> 4, cg = threadIdx.x & 15;
    const int r0 = rg * 4, c0 = cg * 4;
    float acc[4][4] = {};
    for (int k = 0; k < HYPER; k += 4) {
        float4 a[4], b[4];
#pragma unroll
        for (int i = 0; i < 4; i++) a[i] = *(float4*)(sW + (r0 + i) * 132 + k);
#pragma unroll
        for (int j = 0; j < 4; j++) b[j] = *(float4*)(sW + (c0 + j) * 132 + k);
#pragma unroll
        for (int i = 0; i < 4; i++)
#pragma unroll
            for (int j = 0; j < 4; j++)
                acc[i][j] += a[i].x*b[j].x + a[i].y*b[j].y + a[i].z*b[j].z + a[i].w*b[j].w;
    }
    float* Pout = g_P + part * D * D;
#pragma unroll
    for (int i = 0; i < 4; i++)
#pragma unroll
        for (int j = 0; j < 4; j++)
            Pout[(r0 + i) * D + c0 + j] = acc[i][j];
}

// ---------------------------------------------------------------------------
// M = P @ S per partition. grid=(2), block=256.
// ---------------------------------------------------------------------------
__global__ void kM(int parity) {
    __shared__ float sP[D * 68];
    __shared__ float sS[D * 68];
    const int part = blockIdx.x;
    const float* P = g_P + part * D * D;
    const float* S = G_S + (parity * 2 + part) * D * D;
    for (int i = threadIdx.x; i < D * D / 4; i += blockDim.x) {
        int r = i >> 4, c4 = i & 15;
        *(float4*)(sP + r * 68 + c4 * 4) = *(const float4*)(P + r * D + c4 * 4);
        *(float4*)(sS + r * 68 + c4 * 4) = *(const float4*)(S + r * D + c4 * 4);
    }
    __syncthreads();
    const int rg = threadIdx.x >> 4, cg = threadIdx.x & 15;
    const int r0 = rg * 4, c0 = cg * 4;
    float4 acc[4] = {};
    for (int k = 0; k < D; k += 4) {
        float4 a[4], m[4];
#pragma unroll
        for (int i = 0; i < 4; i++) a[i] = *(float4*)(sP + (r0 + i) * 68 + k);
#pragma unroll
        for (int j = 0; j < 4; j++) m[j] = *(float4*)(sS + (k + j) * 68 + c0);
#pragma unroll
        for (int i = 0; i < 4; i++) {
            FMA4(acc[i], a[i].x, m[0]); FMA4(acc[i], a[i].y, m[1]);
            FMA4(acc[i], a[i].z, m[2]); FMA4(acc[i], a[i].w, m[3]);
        }
    }
    float* Mout = g_M + part * D * D;
#pragma unroll
    for (int i = 0; i < 4; i++) *(float4*)(Mout + (r0 + i) * D + c0) = acc[i];
}

// ---------------------------------------------------------------------------
// CSR build: histogram (+ scan-state reset) -> lookback scan -> scatter
// ---------------------------------------------------------------------------
__global__ void kHist(const int* __restrict__ rows) {
    int i = blockIdx.x * blockDim.x + threadIdx.x;
    if (i < SCAN_BLOCKS) g_state[i] = 0;
    int base = i * 4;
    if (base < NNZ_CNT) {
        int4 r = __ldg((const int4*)(rows + base));
        atomicAdd(&G_CNT[r.x], 1);
        atomicAdd(&G_CNT[r.y], 1);
        atomicAdd(&G_CNT[r.z], 1);
        atomicAdd(&G_CNT[r.w], 1);
    }
}

__global__ void __launch_bounds__(1024) kScan() {
    __shared__ int wsum[32];
    __shared__ int s_bt;
    __shared__ int s_run;
    const int t = threadIdx.x, bid = blockIdx.x;
    const int i = bid * 1024 + t;
    int v = (i < N_NODES) ? G_CNT[i] : 0;
    int incl = v;
#pragma unroll
    for (int d = 1; d < 32; d <<= 1) {
        int u = __shfl_up_sync(0xffffffffu, incl, d);
        if ((t & 31) >= d) incl += u;
    }
    if ((t & 31) == 31) wsum[t >> 5] = incl;
    __syncthreads();
    if (t < 32) {
        int w = wsum[t];
        int winc = w;
#pragma unroll
        for (int d = 1; d < 32; d <<= 1) {
            int u = __shfl_up_sync(0xffffffffu, winc, d);
            if (t >= d) winc += u;
        }
        wsum[t] = winc - w;            // exclusive warp offset
        if (t == 31) s_bt = winc;      // block total
    }
    __syncthreads();
    const int blockTotal = s_bt;
    if (t == 0) {
        if (bid == 0) {
            g_state[0] = ((u64t)2 << 32) | (unsigned)blockTotal;
            s_run = 0;
        } else {
            g_state[bid] = ((u64t)1 << 32) | (unsigned)blockTotal;
            __threadfence();
            int run = 0;
            int p = bid - 1;
            while (p >= 0) {
                u64t s;
                do { s = g_state[p]; } while ((s >> 32) == 0);
                run += (int)(unsigned)s;
                if ((s >> 32) == 2) break;
                p--;
            }
            g_state[bid] = ((u64t)2 << 32) | (unsigned)(run + blockTotal);
            __threadfence();
            s_run = run;
        }
    }
    __syncthreads();
    if (i < N_NODES) {
        int base = s_run + (incl - v) + wsum[t >> 5];
        g_offs[i] = base;
        G_CNT[i] = base;               // scatter cursor
    }
    if (i == 0) g_offs[N_NODES] = NNZ_CNT;
}

__global__ void kScatter(const int* __restrict__ rows, const int* __restrict__ cols,
                         const float* __restrict__ vals) {
    int i = blockIdx.x * blockDim.x + threadIdx.x;
    int base = i * 4;
    if (base >= NNZ_CNT) return;
    const u64t pol = mk_evict_first();
    int4 r = __ldg((const int4*)(rows + base));
    int4 c = __ldg((const int4*)(cols + base));
    float4 v = __ldg((const float4*)(vals + base));
    int p0 = atomicAdd(&G_CNT[r.x], 1);
    st_ef8(&g_csr[p0], make_int2(c.x, __float_as_int(v.x)), pol);
    int p1 = atomicAdd(&G_CNT[r.y], 1);
    st_ef8(&g_csr[p1], make_int2(c.y, __float_as_int(v.y)), pol);
    int p2 = atomicAdd(&G_CNT[r.z], 1);
    st_ef8(&g_csr[p2], make_int2(c.z, __float_as_int(v.z)), pol);
    int p3 = atomicAdd(&G_CNT[r.w], 1);
    st_ef8(&g_csr[p3], make_int2(c.w, __float_as_int(v.w)), pol);
}

// ---------------------------------------------------------------------------
// CSR SpMM over fp16 rows in g_hh (emb for layer 0, h1 for layer 1).
// One warp per row; half-warps alternate edges, 2-way unrolled.
// ---------------------------------------------------------------------------
__global__ void __launch_bounds__(256) kSpmm(float* __restrict__ gcn) {
    const int row = (blockIdx.x * blockDim.x + threadIdx.x) >> 5;
    if (row >= N_NODES) return;
    const int lane = threadIdx.x & 31;
    const int half = lane >> 4, l16 = lane & 15;
    const u64t pol = mk_evict_last();
    const int s = __ldg(&g_offs[row]);
    const int e = __ldg(&g_offs[row + 1]);
    float4 acc0 = make_float4(0.f, 0.f, 0.f, 0.f);
    float4 acc1 = make_float4(0.f, 0.f, 0.f, 0.f);
    int j = s + half;
    for (; j + 2 < e; j += 4) {
        int2 cva = __ldcs(&g_csr[j]);
        int2 cvb = __ldcs(&g_csr[j + 2]);
        float va = __int_as_float(cva.y);
        float vb = __int_as_float(cvb.y);
        uint2 ha = ld_el8(g_hh + (size_t)cva.x * D + l16 * 4, pol);
        uint2 hb = ld_el8(g_hh + (size_t)cvb.x * D + l16 * 4, pol);
        float2 a0 = __half22float2(*reinterpret_cast<__half2*>(&ha.x));
        float2 a1 = __half22float2(*reinterpret_cast<__half2*>(&ha.y));
        float2 b0 = __half22float2(*reinterpret_cast<__half2*>(&hb.x));
        float2 b1 = __half22float2(*reinterpret_cast<__half2*>(&hb.y));
        acc0.x += va * a0.x; acc0.y += va * a0.y; acc0.z += va * a1.x; acc0.w += va * a1.y;
        acc1.x += vb * b0.x; acc1.y += vb * b0.y; acc1.z += vb * b1.x; acc1.w += vb * b1.y;
    }
    if (j < e) {
        int2 cv = __ldcs(&g_csr[j]);
        float v = __int_as_float(cv.y);
        uint2 hv = ld_el8(g_hh + (size_t)cv.x * D + l16 * 4, pol);
        float2 f0 = __half22float2(*reinterpret_cast<__half2*>(&hv.x));
        float2 f1 = __half22float2(*reinterpret_cast<__half2*>(&hv.y));
        acc0.x += v * f0.x; acc0.y += v * f0.y; acc0.z += v * f1.x; acc0.w += v * f1.y;
    }
    acc0.x += acc1.x; acc0.y += acc1.y; acc0.z += acc1.z; acc0.w += acc1.w;
    acc0.x += __shfl_xor_sync(0xffffffffu, acc0.x, 16);
    acc0.y += __shfl_xor_sync(0xffffffffu, acc0.y, 16);
    acc0.z += __shfl_xor_sync(0xffffffffu, acc0.z, 16);
    acc0.w += __shfl_xor_sync(0xffffffffu, acc0.w, 16);
    if (half == 0)
        *(float4*)(gcn + (size_t)row * D + l16 * 4) = acc0;
}

// ---------------------------------------------------------------------------
// Partition mapping helper for row-tiled kernels (block = 256 rows)
// ---------------------------------------------------------------------------
struct PartInfo { int part, rowbase, partEnd, localOff; const float* emb; };

__device__ __forceinline__ PartInfo get_part(int b, const float* ue, const float* ie) {
    PartInfo p;
    if (b < UB256) { p.part = 0; p.rowbase = b * 256; p.partEnd = N_USERS; p.localOff = 0; p.emb = ue; }
    else { p.part = 1; p.rowbase = N_USERS + (b - UB256) * 256; p.partEnd = N_NODES; p.localOff = N_USERS; p.emb = ie; }
    return p;
}

// ---------------------------------------------------------------------------
// kS0: S0 = emb^T emb per partition; also emits fp16 emb copy into g_hh
// ---------------------------------------------------------------------------
__global__ void __launch_bounds__(256) kS0(const float* __restrict__ user_emb,
                                           const float* __restrict__ item_emb) {
    __shared__ float sA[64 * D];
    PartInfo p = get_part(blockIdx.x, user_emb, item_emb);
    const int tid = threadIdx.x;
    const int ag = tid >> 4, bg = tid & 15;
    const u64t pol = mk_evict_last();
    p4 sacc[4] = {};
    for (int t = 0; t < 4; t++) {
        const int tb = p.rowbase + t * 64;
        for (int i = tid; i < 1024; i += 256) {
            int r = i >> 4, c4 = i & 15;
            int gr = tb + r;
            float4 v = make_float4(0.f, 0.f, 0.f, 0.f);
            if (gr < p.partEnd) {
                v = __ldg((const float4*)(p.emb + (size_t)(gr - p.localOff) * D + c4 * 4));
                st_el8(g_hh + (size_t)gr * D + c4 * 4, f4_to_h4(v), pol);
            }
            *(float4*)(sA + r * D + c4 * 4) = v;
        }
        __syncthreads();
#pragma unroll 4
        for (int r = 0; r < 64; r++) {
            float4 a4 = *(float4*)(sA + r * D + ag * 4);
            ulonglong2 b2 = *(const ulonglong2*)(sA + r * D + bg * 4);
            u64t s;
            s = pk2(a4.x); fma2(sacc[0].lo, s, b2.x); fma2(sacc[0].hi, s, b2.y);
            s = pk2(a4.y); fma2(sacc[1].lo, s, b2.x); fma2(sacc[1].hi, s, b2.y);
            s = pk2(a4.z); fma2(sacc[2].lo, s, b2.x); fma2(sacc[2].hi, s, b2.y);
            s = pk2(a4.w); fma2(sacc[3].lo, s, b2.x); fma2(sacc[3].hi, s, b2.y);
        }
        __syncthreads();
    }
    float* Sdst = G_S + p.part * D * D;   // parity 0
#pragma unroll
    for (int j = 0; j < 4; j++)
        red_add_v4(Sdst + (ag * 4 + j) * D + bg * 4, unpk(sacc[j]));
}

// ---------------------------------------------------------------------------
// Epilogue (R13-proven form: sM in smem, natural regs/occupancy).
// layer==0: hg0 = emb@M0; h1 = gcn0+hg0 -> g_hh (fp16, evict_last);
//           accumulate S1 = emb^T h1 (exact fp32 from smem).
// layer==1: hg1 = emb@M1; h2 = gcn1+hg1; hidden_sum = emb + h1(fp16) + h2.
// ---------------------------------------------------------------------------
__global__ void __launch_bounds__(256) kEpi(const float* __restrict__ user_emb,
                                            const float* __restrict__ item_emb,
                                            const float* __restrict__ gcn,
                                            float* __restrict__ hg_out,
                                            float* __restrict__ hidden_sum,
                                            int layer) {
    __shared__ float sM[D * D];
    __shared__ float sA[64 * D];
    __shared__ float sH[64 * D];
    PartInfo p = get_part(blockIdx.x, user_emb, item_emb);
    const int tid = threadIdx.x;
    const u64t pol = mk_evict_last();
    for (int i = tid; i < D * D / 4; i += 256)
        *(float4*)(sM + i * 4) = *(const float4*)(g_M + p.part * D * D + i * 4);
    const int rg = tid >> 4, cg = tid & 15;
    const int r0 = rg * 4, c0 = cg * 4;
    p4 sacc[4] = {};
    for (int t = 0; t < 4; t++) {
        const int tb = p.rowbase + t * 64;
        for (int i = tid; i < 1024; i += 256) {
            int r = i >> 4, c4 = i & 15;
            int gr = tb + r;
            float4 v = make_float4(0.f, 0.f, 0.f, 0.f);
            if (gr < p.partEnd)
                v = __ldg((const float4*)(p.emb + (size_t)(gr - p.localOff) * D + c4 * 4));
            *(float4*)(sA + r * D + c4 * 4) = v;
        }
        __syncthreads();
        // hg tile: acc = sA(rows) @ sM, packed f32x2
        p4 acc[4] = {};
        for (int k = 0; k < D; k += 4) {
            float4 a[4]; ulonglong2 m[4];
#pragma unroll
            for (int i = 0; i < 4; i++) a[i] = *(float4*)(sA + (r0 + i) * D + k);
#pragma unroll
            for (int j = 0; j < 4; j++) m[j] = *(const ulonglong2*)(sM + (k + j) * D + c0);
#pragma unroll
            for (int i = 0; i < 4; i++) {
                u64t s;
                s = pk2(a[i].x); fma2(acc[i].lo, s, m[0].x); fma2(acc[i].hi, s, m[0].y);
                s = pk2(a[i].y); fma2(acc[i].lo, s, m[1].x); fma2(acc[i].hi, s, m[1].y);
                s = pk2(a[i].z); fma2(acc[i].lo, s, m[2].x); fma2(acc[i].hi, s, m[2].y);
                s = pk2(a[i].w); fma2(acc[i].lo, s, m[3].x); fma2(acc[i].hi, s, m[3].y);
            }
        }
#pragma unroll
        for (int i = 0; i < 4; i++) {
            int gr = tb + r0 + i;
            if (gr < p.partEnd) {
                size_t idx = (size_t)gr * D + c0;
                float4 hg = unpk(acc[i]);
                float4 g = __ldg((const float4*)(gcn + idx));
                *(float4*)(hg_out + idx) = hg;
                float4 hn = make_float4(hg.x + g.x, hg.y + g.y, hg.z + g.z, hg.w + g.w);
                if (layer == 0) {
                    st_el8(g_hh + idx, f4_to_h4(hn), pol);   // h1 fp16, keep resident
                    *(float4*)(sH + (r0 + i) * D + c0) = hn;
                } else {
                    uint2 hu = *(const uint2*)(g_hh + idx);  // h1 fp16
                    float2 h1a = __half22float2(*reinterpret_cast<__half2*>(&hu.x));
                    float2 h1b = __half22float2(*reinterpret_cast<__half2*>(&hu.y));
                    float4 e4 = *(float4*)(sA + (r0 + i) * D + c0);
                    float4 hs = make_float4(e4.x + h1a.x + hn.x, e4.y + h1a.y + hn.y,
                                            e4.z + h1b.x + hn.z, e4.w + h1b.y + hn.w);
                    *(float4*)(hidden_sum + idx) = hs;
                }
            } else if (layer == 0) {
                *(float4*)(sH + (r0 + i) * D + c0) = make_float4(0.f, 0.f, 0.f, 0.f);
            }
        }
        __syncthreads();
        if (layer == 0) {
#pragma unroll 4
            for (int r = 0; r < 64; r++) {
                float4 a4 = *(float4*)(sA + r * D + rg * 4);
                ulonglong2 h2 = *(const ulonglong2*)(sH + r * D + cg * 4);
                u64t s;
                s = pk2(a4.x); fma2(sacc[0].lo, s, h2.x); fma2(sacc[0].hi, s, h2.y);
                s = pk2(a4.y); fma2(sacc[1].lo, s, h2.x); fma2(sacc[1].hi, s, h2.y);
                s = pk2(a4.z); fma2(sacc[2].lo, s, h2.x); fma2(sacc[2].hi, s, h2.y);
                s = pk2(a4.w); fma2(sacc[3].lo, s, h2.x); fma2(sacc[3].hi, s, h2.y);
            }
            __syncthreads();
        }
    }
    if (layer == 0) {
        float* Sdst = G_S + (2 + p.part) * D * D;     // parity 1
#pragma unroll
        for (int j = 0; j < 4; j++)
            red_add_v4(Sdst + (rg * 4 + j) * D + cg * 4, unpk(sacc[j]));
    }
}

// ---------------------------------------------------------------------------
extern "C" void kernel_launch(void* const* d_in, const int* in_sizes, int n_in,
                              void* d_out, int out_size) {
    const float* user_emb = (const float*)d_in[0];
    const float* item_emb = (const float*)d_in[1];
    const float* user_w   = (const float*)d_in[2];
    const float* item_w   = (const float*)d_in[3];
    const float* adj_vals = (const float*)d_in[4];
    const int*   adj_rows = (const int*)d_in[5];
    const int*   adj_cols = (const int*)d_in[6];
    float* out = (float*)d_out;

    // Lazily created side stream + events (first call precedes graph capture;
    // fork/join via events is graph-capture legal). No device memory involved.
    static cudaStream_t s2 = nullptr;
    static cudaEvent_t evZ = nullptr, evS0 = nullptr, evM0 = nullptr,
                       evE0 = nullptr, evM1 = nullptr;
    if (!s2) {
        cudaStreamCreateWithFlags(&s2, cudaStreamNonBlocking);
        cudaEventCreateWithFlags(&evZ, cudaEventDisableTiming);
        cudaEventCreateWithFlags(&evS0, cudaEventDisableTiming);
        cudaEventCreateWithFlags(&evM0, cudaEventDisableTiming);
        cudaEventCreateWithFlags(&evE0, cudaEventDisableTiming);
        cudaEventCreateWithFlags(&evM1, cudaEventDisableTiming);
    }

    // d_out layout (floats): [0) hidden_sum(user_out|item_out) 19.2M
    //                        [19.2M) gcn_hidden L0,L1           38.4M
    //                        [57.6M) hgnn_hidden L0,L1          38.4M
    float* gcn0 = out + (size_t)NODESD * 1;
    float* gcn1 = out + (size_t)NODESD * 2;
    float* hg0  = out + (size_t)NODESD * 3;
    float* hg1  = out + (size_t)NODESD * 4;

    void* zAddr = nullptr; cudaGetSymbolAddress(&zAddr, g_zblob);

    const int EB4 = (NNZ_CNT / 4 + 255) / 256;   // 3907

    // Launch order tuned so ncu's "-s 5 -c 1" capture lands on kSpmm
    // (R14 captured the kernel submitted 5th-in-code; kS0 now sits there,
    //  pushing kSpmm into the captured slot).
    cudaMemsetAsync(zAddr, 0, sizeof(g_zblob));
    cudaEventRecord(evZ, 0);
    kHist<<<EB4, 256>>>(adj_rows);
    kScan<<<SCAN_BLOCKS, 1024>>>();
    // kS0 on side stream (needs only the zeroed blob); emits fp16 emb -> g_hh
    cudaStreamWaitEvent(s2, evZ, 0);
    kS0<<<GRID_ROWS, 256, 0, s2>>>(user_emb, item_emb);
    cudaEventRecord(evS0, s2);
    kScatter<<<EB4, 256>>>(adj_rows, adj_cols, adj_vals);
    // layer-0 SpMM (after scatter [stream] + g_hh [event])   <-- profiled slot
    cudaStreamWaitEvent(0, evS0, 0);
    kSpmm<<<(N_NODES * 32) / 256, 256>>>(gcn0);
    // kP, kM0 on side stream (2-block kernels; overlap spmm0 harmlessly)
    kP<<<2, 256, 0, s2>>>(user_w, item_w);
    kM<<<2, 256, 0, s2>>>(0);
    cudaEventRecord(evM0, s2);
    // epilogue 0 (needs gcn0 [stream] + M0 [event]); writes h1 fp16 + S1
    cudaStreamWaitEvent(0, evM0, 0);
    kEpi<<<GRID_ROWS, 256>>>(user_emb, item_emb, gcn0, hg0, out, 0);
    cudaEventRecord(evE0, 0);
    // kM1 on side stream (needs S1 from epi0)
    cudaStreamWaitEvent(s2, evE0, 0);
    kM<<<2, 256, 0, s2>>>(1);
    cudaEventRecord(evM1, s2);
    // layer-1 SpMM (g_hh = h1, written by epi0 on this stream)
    kSpmm<<<(N_NODES * 32) / 256, 256>>>(gcn1);
    // epilogue 1 (needs gcn1 [stream] + M1 [event])
    cudaStreamWaitEvent(0, evM1, 0);
    kEpi<<<GRID_ROWS, 256>>>(user_emb, item_emb, gcn1, hg1, out, 1);
}